// round 6
// baseline (speedup 1.0000x reference)
#include <cuda_runtime.h>
#include <cuda_bf16.h>
#include <math.h>
#include <stdint.h>

// Problem constants
#define KK    64
#define DD    512
#define TT    128
#define BB    512
#define BOS_T 63
#define EOS_T 62
#define LOG64 4.158883083359672f
#define STR   68              // padded SMEM row stride in 4B words (272B)

// Global scratch: exp(wb)/64, masked. [512 seq][128 t][64 k] f32 = 16 MB
__device__ float g_swb[(size_t)BB * TT * KK];

__device__ __forceinline__ uint32_t pk(float a, float b) {
    __nv_bfloat162 h = __floats2bfloat162_rn(a, b);
    return *reinterpret_cast<uint32_t*>(&h);
}

__device__ __forceinline__ void mma16816(float* c, uint32_t a0, uint32_t a1,
                                         uint32_t a2, uint32_t a3,
                                         uint32_t b0, uint32_t b1) {
    asm volatile(
        "mma.sync.aligned.m16n8k16.row.col.f32.bf16.bf16.f32 "
        "{%0,%1,%2,%3}, {%4,%5,%6,%7}, {%8,%9}, {%0,%1,%2,%3};"
        : "+f"(c[0]), "+f"(c[1]), "+f"(c[2]), "+f"(c[3])
        : "r"(a0), "r"(a1), "r"(a2), "r"(a3), "r"(b0), "r"(b1));
}

// ---------------------------------------------------------------------------
// Kernel 1: emission. 1024 CTAs = (seq, half). M=64 tile, K=512 in 4 chunks.
// Gathers E rows -> bf16 SMEM, bf16 MMA, writes exp(wb)/64 (BOS/EOS cols 0)
// to g_swb. Small SMEM + regs -> 3 CTAs/SM for latency overlap.
// ---------------------------------------------------------------------------
__global__ __launch_bounds__(256, 3)
void emit_kernel(const float* __restrict__ ThetaB,
                 const float* __restrict__ E,
                 const int*   __restrict__ words)
{
    __shared__ uint32_t A32[64 * STR];
    __shared__ uint32_t B32[64 * STR];

    const int tid  = threadIdx.x;
    const int wid  = tid >> 5, lane = tid & 31;
    const int g    = lane >> 2, t4 = lane & 3;
    const int blk  = blockIdx.x;
    const int b    = blk >> 1, h = blk & 1;

    const int mt = wid & 3, nh = wid >> 2;   // warp: m-tile 0..3, n-half 0..1
    const int m0 = mt * 16;

    // gather: 4 threads per row, 32 f32 each per chunk
    const int row = tid >> 2, q = tid & 3;
    const int word = words[b * TT + h * 64 + row];
    const float* eptr = E + (size_t)word * DD + q * 32;
    const float* tptr = ThetaB + row * DD + q * 32;

    float acc[4][4];
#pragma unroll
    for (int nt = 0; nt < 4; ++nt)
#pragma unroll
        for (int r = 0; r < 4; ++r) acc[nt][r] = 0.f;

    for (int c = 0; c < 4; ++c) {
        if (c) __syncthreads();
        const float4* e4 = (const float4*)(eptr + c * 128);
        const float4* h4 = (const float4*)(tptr + c * 128);
#pragma unroll
        for (int j = 0; j < 4; ++j) {
            float4 f0 = e4[2 * j], f1 = e4[2 * j + 1];
            *(uint4*)((char*)A32 + row * 272 + q * 64 + j * 16) =
                make_uint4(pk(f0.x, f0.y), pk(f0.z, f0.w), pk(f1.x, f1.y), pk(f1.z, f1.w));
            float4 g0 = h4[2 * j], g1 = h4[2 * j + 1];
            *(uint4*)((char*)B32 + row * 272 + q * 64 + j * 16) =
                make_uint4(pk(g0.x, g0.y), pk(g0.z, g0.w), pk(g1.x, g1.y), pk(g1.z, g1.w));
        }
        __syncthreads();

#pragma unroll
        for (int s = 0; s < 8; ++s) {
            const uint32_t a0 = A32[(m0 + g)     * STR + s * 8 + t4];
            const uint32_t a1 = A32[(m0 + 8 + g) * STR + s * 8 + t4];
            const uint32_t a2 = A32[(m0 + g)     * STR + s * 8 + t4 + 4];
            const uint32_t a3 = A32[(m0 + 8 + g) * STR + s * 8 + t4 + 4];
#pragma unroll
            for (int nt = 0; nt < 4; ++nt) {
                const int ntg = nh * 4 + nt;
                const uint32_t b0 = B32[(ntg * 8 + g) * STR + s * 8 + t4];
                const uint32_t b1 = B32[(ntg * 8 + g) * STR + s * 8 + t4 + 4];
                mma16816(acc[nt], a0, a1, a2, a3, b0, b1);
            }
        }
    }

    // epilogue: exp/64, mask cols 62,63, write to g_swb
    const float inv = 1.0f / 64.0f;
    const int t0 = h * 64 + m0 + g, t1 = t0 + 8;
    float* obase = g_swb + (size_t)b * TT * KK;
#pragma unroll
    for (int nt = 0; nt < 4; ++nt) {
        const int col = (nh * 4 + nt) * 8 + t4 * 2;
        const bool msk = (col == EOS_T);
        float2 v0, v1;
        v0.x = msk ? 0.f : __expf(acc[nt][0]) * inv;
        v0.y = msk ? 0.f : __expf(acc[nt][1]) * inv;
        v1.x = msk ? 0.f : __expf(acc[nt][2]) * inv;
        v1.y = msk ? 0.f : __expf(acc[nt][3]) * inv;
        *(float2*)(obase + t0 * KK + col) = v0;
        *(float2*)(obase + t1 * KK + col) = v1;
    }
}

// ---------------------------------------------------------------------------
// Kernel 2: tagged closed form + forward recursion. 512 CTAs (one/seq),
// 256 threads, ~35 KB SMEM, 4 CTAs/SM -> whole batch resident in one wave.
// ---------------------------------------------------------------------------
__global__ __launch_bounds__(256, 4)
void forward_kernel(const float* __restrict__ WA,
                    const int*   __restrict__ tags,
                    float*       __restrict__ out)
{
    __shared__ float swb[127 * STR];     // rows 1..126 used
    __shared__ float sal[2 * KK];
    __shared__ float sred[32];

    const int tid  = threadIdx.x;
    const int wid  = tid >> 5, lane = tid & 31;
    const int g    = lane >> 2, t4 = lane & 3;
    const int b    = blockIdx.x;

    // prefetch swb rows 1..126 (2 threads/row, 8 float4 each)
    {
        const int r = (tid >> 1) + 1, half = tid & 1;
        if (r <= 126) {
            const float4* src = (const float4*)(g_swb + ((size_t)b * TT + r) * KK + half * 32);
            float4* dst = (float4*)(swb + r * STR + half * 32);
#pragma unroll
            for (int j = 0; j < 8; ++j) dst[j] = src[j];
        }
    }
    __syncthreads();

    // tagged closed form
    float tagc = 0.f;
    if (tid >= 1 && tid <= 126) {
        const int ct = tags[b * TT + tid];
        const int pt = (tid == 1) ? BOS_T : tags[b * TT + tid - 1];
        tagc = __logf(swb[tid * STR + ct]) + LOG64 + WA[pt * KK + ct];
    } else if (tid == 127) {
        tagc = WA[tags[b * TT + 126] * KK + EOS_T];
    }
#pragma unroll
    for (int o = 16; o > 0; o >>= 1) tagc += __shfl_down_sync(0xffffffffu, tagc, o);
    if (lane == 0) sred[wid] = tagc;
    __syncthreads();
    if (tid == 0) {
        float s = 0.f;
        for (int w = 0; w < 8; ++w) s += sred[w];
        sred[8] = s;
    }

    // forward recursion: output k = 8*wid + g, j-range split over t4
    const int fk = wid * 8 + g;
    float Areg[16];
#pragma unroll
    for (int jj = 0; jj < 16; ++jj)
        Areg[jj] = __expf(WA[(t4 * 16 + jj) * KK + fk]);

    if (t4 == 0) sal[fk] = __expf(WA[BOS_T * KK + fk]) * swb[1 * STR + fk];
    __syncthreads();

    int buf = 0;
    for (int t = 2; t <= 126; ++t) {
        const float4* av = (const float4*)(sal + buf * KK + t4 * 16);
        float s0 = 0.f, s1 = 0.f, s2 = 0.f, s3 = 0.f;
#pragma unroll
        for (int jj = 0; jj < 4; ++jj) {
            const float4 v = av[jj];
            s0 = fmaf(v.x, Areg[4 * jj + 0], s0);
            s1 = fmaf(v.y, Areg[4 * jj + 1], s1);
            s2 = fmaf(v.z, Areg[4 * jj + 2], s2);
            s3 = fmaf(v.w, Areg[4 * jj + 3], s3);
        }
        float s = (s0 + s1) + (s2 + s3);
        s += __shfl_xor_sync(0xffffffffu, s, 1);
        s += __shfl_xor_sync(0xffffffffu, s, 2);
        if (t4 == 0) sal[(buf ^ 1) * KK + fk] = s * swb[t * STR + fk];
        __syncthreads();
        buf ^= 1;
    }

    float contrib = 0.f;
    if (tid < 64) contrib = sal[buf * KK + tid] * __expf(WA[tid * KK + EOS_T]);
#pragma unroll
    for (int o = 16; o > 0; o >>= 1) contrib += __shfl_down_sync(0xffffffffu, contrib, o);
    if (tid < 64 && lane == 0) sred[16 + wid] = contrib;
    __syncthreads();
    if (tid == 0)
        out[b] = sred[8] - (__logf(sred[16] + sred[17]) + 126.0f * LOG64);
}

// ---------------------------------------------------------------------------
// Inputs: WA[64*64] f32, ThetaB[64*512] f32, E[100000*512] f32,
//         words[512*128] i32, tags[512*128] i32  ->  out f32[512]
// ---------------------------------------------------------------------------
extern "C" void kernel_launch(void* const* d_in, const int* in_sizes, int n_in,
                              void* d_out, int out_size)
{
    const float* WA     = (const float*)d_in[0];
    const float* ThetaB = (const float*)d_in[1];
    const float* E      = (const float*)d_in[2];
    const int*   words  = (const int*)d_in[3];
    const int*   tags   = (const int*)d_in[4];
    float*       out    = (float*)d_out;

    emit_kernel<<<1024, 256>>>(ThetaB, E, words);
    forward_kernel<<<512, 256>>>(WA, tags, out);
}

// round 7
// speedup vs baseline: 1.3702x; 1.3702x over previous
#include <cuda_runtime.h>
#include <cuda_bf16.h>
#include <math.h>
#include <stdint.h>

// Problem constants
#define KK    64
#define DD    512
#define TT    128
#define BB    512
#define BOS_T 63
#define EOS_T 62
#define LOG64 4.158883083359672f
#define STR   68              // padded SMEM row stride in 4B words (272B)

#define NSEG  ((size_t)BB * TT * KK)
// Raw emission partial sums, two K-halves: [kc][seq][t][k] f32 = 32 MB
__device__ float g_wbp[2 * NSEG];

__device__ __forceinline__ uint32_t pk(float a, float b) {
    __nv_bfloat162 h = __floats2bfloat162_rn(a, b);
    return *reinterpret_cast<uint32_t*>(&h);
}

__device__ __forceinline__ void mma16816(float* c, uint32_t a0, uint32_t a1,
                                         uint32_t a2, uint32_t a3,
                                         uint32_t b0, uint32_t b1) {
    asm volatile(
        "mma.sync.aligned.m16n8k16.row.col.f32.bf16.bf16.f32 "
        "{%0,%1,%2,%3}, {%4,%5,%6,%7}, {%8,%9}, {%0,%1,%2,%3};"
        : "+f"(c[0]), "+f"(c[1]), "+f"(c[2]), "+f"(c[3])
        : "r"(a0), "r"(a1), "r"(a2), "r"(a3), "r"(b0), "r"(b1));
}

// ---------------------------------------------------------------------------
// Kernel 1: emission partials. 2048 CTAs = (seq, t-half, k-half).
// Each CTA: M=64 t-rows x N=64 tags over K=256 dims (2 chunks of 128).
// Writes RAW f32 partial dot products (no exp) to its disjoint region.
// ---------------------------------------------------------------------------
__global__ __launch_bounds__(256, 3)
void emit_kernel(const float* __restrict__ ThetaB,
                 const float* __restrict__ E,
                 const int*   __restrict__ words)
{
    __shared__ uint32_t A32[64 * STR];
    __shared__ uint32_t B32[64 * STR];

    const int tid  = threadIdx.x;
    const int wid  = tid >> 5, lane = tid & 31;
    const int g    = lane >> 2, t4 = lane & 3;
    const int blk  = blockIdx.x;
    const int kc   = blk & 1;
    const int h    = (blk >> 1) & 1;
    const int b    = blk >> 2;

    const int mt = wid & 3, nh = wid >> 2;   // warp: m-tile 0..3, n-half 0..1
    const int m0 = mt * 16;

    // gather: 4 threads per row, 32 f32 each per chunk
    const int row = tid >> 2, q = tid & 3;
    const int word = words[b * TT + h * 64 + row];
    const float* eptr = E + (size_t)word * DD + kc * 256 + q * 32;
    const float* tptr = ThetaB + row * DD + kc * 256 + q * 32;

    float acc[4][4];
#pragma unroll
    for (int nt = 0; nt < 4; ++nt)
#pragma unroll
        for (int r = 0; r < 4; ++r) acc[nt][r] = 0.f;

    for (int c = 0; c < 2; ++c) {
        if (c) __syncthreads();
        const float4* e4 = (const float4*)(eptr + c * 128);
        const float4* h4 = (const float4*)(tptr + c * 128);
#pragma unroll
        for (int j = 0; j < 4; ++j) {
            float4 f0 = e4[2 * j], f1 = e4[2 * j + 1];
            *(uint4*)((char*)A32 + row * 272 + q * 64 + j * 16) =
                make_uint4(pk(f0.x, f0.y), pk(f0.z, f0.w), pk(f1.x, f1.y), pk(f1.z, f1.w));
            float4 g0 = h4[2 * j], g1 = h4[2 * j + 1];
            *(uint4*)((char*)B32 + row * 272 + q * 64 + j * 16) =
                make_uint4(pk(g0.x, g0.y), pk(g0.z, g0.w), pk(g1.x, g1.y), pk(g1.z, g1.w));
        }
        __syncthreads();

#pragma unroll
        for (int s = 0; s < 8; ++s) {
            const uint32_t a0 = A32[(m0 + g)     * STR + s * 8 + t4];
            const uint32_t a1 = A32[(m0 + 8 + g) * STR + s * 8 + t4];
            const uint32_t a2 = A32[(m0 + g)     * STR + s * 8 + t4 + 4];
            const uint32_t a3 = A32[(m0 + 8 + g) * STR + s * 8 + t4 + 4];
#pragma unroll
            for (int nt = 0; nt < 4; ++nt) {
                const int ntg = nh * 4 + nt;
                const uint32_t b0 = B32[(ntg * 8 + g) * STR + s * 8 + t4];
                const uint32_t b1 = B32[(ntg * 8 + g) * STR + s * 8 + t4 + 4];
                mma16816(acc[nt], a0, a1, a2, a3, b0, b1);
            }
        }
    }

    // write raw partials to disjoint region
    float* obase = g_wbp + kc * NSEG + (size_t)b * TT * KK;
    const int t0 = h * 64 + m0 + g, t1 = t0 + 8;
#pragma unroll
    for (int nt = 0; nt < 4; ++nt) {
        const int col = (nh * 4 + nt) * 8 + t4 * 2;
        *(float2*)(obase + t0 * KK + col) = make_float2(acc[nt][0], acc[nt][1]);
        *(float2*)(obase + t1 * KK + col) = make_float2(acc[nt][2], acc[nt][3]);
    }
}

// ---------------------------------------------------------------------------
// Kernel 2: one WARP per sequence, no block barriers.
// Stage: swb[t][k] = exp(p0+p1)/64 (cols 62,63 zeroed) into SMEM.
// Tagged closed form + 125-step forward recursion; each thread owns outputs
// k=lane and k=lane+32 with both A columns in registers (128 regs).
// ---------------------------------------------------------------------------
__global__ __launch_bounds__(32)
void forward_kernel(const float* __restrict__ WA,
                    const int*   __restrict__ tags,
                    float*       __restrict__ out)
{
    __shared__ __align__(16) float swb_s[126 * KK];   // rows t=1..126
    __shared__ __align__(16) float sal[2][KK];

    const int lane = threadIdx.x;
    const int b    = blockIdx.x;
    const float inv = 1.0f / 64.0f;

    // ---- stage: sum partials, exp, scale, mask ----
    const float4* s0 = (const float4*)(g_wbp + (size_t)b * TT * KK + KK);
    const float4* s1 = (const float4*)(g_wbp + NSEG + (size_t)b * TT * KK + KK);
    for (int i = lane; i < 126 * 16; i += 32) {
        float4 x = s0[i], y = s1[i];
        float4 v;
        v.x = __expf(x.x + y.x) * inv;
        v.y = __expf(x.y + y.y) * inv;
        v.z = __expf(x.z + y.z) * inv;
        v.w = __expf(x.w + y.w) * inv;
        if ((i & 15) == 15) { v.z = 0.f; v.w = 0.f; }   // k = 62, 63
        ((float4*)swb_s)[i] = v;
    }

    // ---- A columns for k=lane and k=lane+32 in registers ----
    float A0[KK], A1[KK];
#pragma unroll
    for (int j = 0; j < KK; ++j) {
        A0[j] = __expf(WA[j * KK + lane]);
        A1[j] = __expf(WA[j * KK + lane + 32]);
    }
    __syncwarp();

    // ---- tagged closed form ----
    float tagc = 0.f;
    for (int t = lane + 1; t <= 126; t += 32) {
        const int ct = tags[b * TT + t];
        const int pt = (t == 1) ? BOS_T : tags[b * TT + t - 1];
        tagc += __logf(swb_s[(t - 1) * KK + ct]) + LOG64 + WA[pt * KK + ct];
    }
    if (lane == 0) tagc += WA[tags[b * TT + 126] * KK + EOS_T];
#pragma unroll
    for (int o = 16; o > 0; o >>= 1) tagc += __shfl_down_sync(0xffffffffu, tagc, o);
    const float tagged = tagc;                         // valid on lane 0

    // ---- forward recursion ----
    float a0 = A0[BOS_T] * swb_s[lane];                // t=1 row at offset 0
    float a1 = A1[BOS_T] * swb_s[lane + 32];

    int buf = 0;
    for (int t = 2; t <= 126; ++t) {
        sal[buf][lane] = a0;
        sal[buf][lane + 32] = a1;
        __syncwarp();
        const float4* av = (const float4*)sal[buf];
        float p0a = 0.f, p1a = 0.f, p2a = 0.f, p3a = 0.f;
        float q0a = 0.f, q1a = 0.f, q2a = 0.f, q3a = 0.f;
#pragma unroll
        for (int jj = 0; jj < 16; ++jj) {
            const float4 v = av[jj];
            p0a = fmaf(v.x, A0[4 * jj + 0], p0a);
            p1a = fmaf(v.y, A0[4 * jj + 1], p1a);
            p2a = fmaf(v.z, A0[4 * jj + 2], p2a);
            p3a = fmaf(v.w, A0[4 * jj + 3], p3a);
            q0a = fmaf(v.x, A1[4 * jj + 0], q0a);
            q1a = fmaf(v.y, A1[4 * jj + 1], q1a);
            q2a = fmaf(v.z, A1[4 * jj + 2], q2a);
            q3a = fmaf(v.w, A1[4 * jj + 3], q3a);
        }
        const float* eb = swb_s + (t - 1) * KK;
        a0 = ((p0a + p1a) + (p2a + p3a)) * eb[lane];
        a1 = ((q0a + q1a) + (q2a + q3a)) * eb[lane + 32];
        buf ^= 1;
    }

    float contrib = a0 * __expf(WA[lane * KK + EOS_T])
                  + a1 * __expf(WA[(lane + 32) * KK + EOS_T]);
#pragma unroll
    for (int o = 16; o > 0; o >>= 1) contrib += __shfl_down_sync(0xffffffffu, contrib, o);

    if (lane == 0)
        out[b] = tagged - (__logf(contrib) + 126.0f * LOG64);
}

// ---------------------------------------------------------------------------
// Inputs: WA[64*64] f32, ThetaB[64*512] f32, E[100000*512] f32,
//         words[512*128] i32, tags[512*128] i32  ->  out f32[512]
// ---------------------------------------------------------------------------
extern "C" void kernel_launch(void* const* d_in, const int* in_sizes, int n_in,
                              void* d_out, int out_size)
{
    const float* WA     = (const float*)d_in[0];
    const float* ThetaB = (const float*)d_in[1];
    const float* E      = (const float*)d_in[2];
    const int*   words  = (const int*)d_in[3];
    const int*   tags   = (const int*)d_in[4];
    float*       out    = (float*)d_out;

    emit_kernel<<<2048, 256>>>(ThetaB, E, words);
    forward_kernel<<<512, 32>>>(WA, tags, out);
}